// round 1
// baseline (speedup 1.0000x reference)
#include <cuda_runtime.h>
#include <math.h>

#define Nn 16
#define Cc 512
#define C4 128
#define QKC 16
#define LLEN 1024
#define EPSf 1e-5f

// ---------------- scratch (device globals; no allocation allowed) ----------------
__device__ float g_value[Nn * C4 * LLEN];                 // 8 MB   proj_value
__device__ float g_qk[2 * 2 * Nn * QKC * LLEN];           // 4 MB   [q/k][pyr][b][qc][l]
__device__ float g_attn[2 * Nn * LLEN * LLEN];            // 134 MB [pyr][b][m][l] probabilities
__device__ float g_cat[Nn * 3 * C4 * LLEN];               // 25 MB  concat of pyramid outputs
__device__ float g_y[Nn * Cc * LLEN];                     // 33 MB  conv output pre-BN
__device__ float g_stats[Cc * 2];                         // per-channel mean, scale*rstd

__device__ __forceinline__ int qk_idx(int g, int py, int b, int qc, int l) {
    return (((g * 2 + py) * Nn + b) * QKC + qc) * LLEN + l;
}

// ---------------- K1: value projection GEMM: out = value_w(128x512) @ x(b,512,1024) + b ----
__global__ void k_value_proj(const float* __restrict__ x,
                             const float* __restrict__ w,
                             const float* __restrict__ bias) {
    __shared__ float As[32 * 68];
    __shared__ float Bs[32 * 68];
    const int b  = blockIdx.z;
    const int m0 = blockIdx.y * 64;   // out channel tile
    const int n0 = blockIdx.x * 64;   // l tile
    const float* xb = x + b * Cc * LLEN;
    const int t  = threadIdx.x;
    const int ty = t >> 4, tx = t & 15;
    const int am = t >> 2, akq = (t & 3) * 8;
    const int bk = t >> 3, bnq = (t & 7) * 8;
    float acc[4][4] = {};

    for (int kc = 0; kc < Cc / 32; kc++) {
        const int k0 = kc * 32;
        __syncthreads();
        float4 a0 = *(const float4*)&w[(m0 + am) * Cc + k0 + akq];
        float4 a1 = *(const float4*)&w[(m0 + am) * Cc + k0 + akq + 4];
        As[(akq + 0) * 68 + am] = a0.x; As[(akq + 1) * 68 + am] = a0.y;
        As[(akq + 2) * 68 + am] = a0.z; As[(akq + 3) * 68 + am] = a0.w;
        As[(akq + 4) * 68 + am] = a1.x; As[(akq + 5) * 68 + am] = a1.y;
        As[(akq + 6) * 68 + am] = a1.z; As[(akq + 7) * 68 + am] = a1.w;
        float4 b0 = *(const float4*)&xb[(k0 + bk) * LLEN + n0 + bnq];
        float4 b1 = *(const float4*)&xb[(k0 + bk) * LLEN + n0 + bnq + 4];
        *(float4*)&Bs[bk * 68 + bnq]     = b0;
        *(float4*)&Bs[bk * 68 + bnq + 4] = b1;
        __syncthreads();
#pragma unroll
        for (int k = 0; k < 32; k++) {
            float4 av = *(const float4*)&As[k * 68 + ty * 4];
            float4 bv = *(const float4*)&Bs[k * 68 + tx * 4];
            acc[0][0] += av.x * bv.x; acc[0][1] += av.x * bv.y; acc[0][2] += av.x * bv.z; acc[0][3] += av.x * bv.w;
            acc[1][0] += av.y * bv.x; acc[1][1] += av.y * bv.y; acc[1][2] += av.y * bv.z; acc[1][3] += av.y * bv.w;
            acc[2][0] += av.z * bv.x; acc[2][1] += av.z * bv.y; acc[2][2] += av.z * bv.z; acc[2][3] += av.z * bv.w;
            acc[3][0] += av.w * bv.x; acc[3][1] += av.w * bv.y; acc[3][2] += av.w * bv.z; acc[3][3] += av.w * bv.w;
        }
    }
#pragma unroll
    for (int i = 0; i < 4; i++) {
        const int c = m0 + ty * 4 + i;
        const float bs = bias[c];
        float4 o;
        o.x = acc[i][0] + bs; o.y = acc[i][1] + bs; o.z = acc[i][2] + bs; o.w = acc[i][3] + bs;
        *(float4*)&g_value[(b * C4 + c) * LLEN + n0 + tx * 4] = o;
    }
}

// ---------------- K2: per-batch pooling + rce + q/k feats + bilinear upsample -------------
// sz=1 pyramid is skipped entirely: constant energy => uniform attention => out = mean(value)
__global__ void k_prep(const float* __restrict__ x,
                       const float* __restrict__ rce_w, const float* __restrict__ rce_b,
                       const float* __restrict__ qw, const float* __restrict__ qb,
                       const float* __restrict__ kw, const float* __restrict__ kb) {
    __shared__ float sp4[Cc * 16];         // pooled 4x4, 32KB
    __shared__ float f4[C4 * 16];          // rce feat sz=4
    __shared__ float f2[C4 * 4];           // rce feat sz=2
    __shared__ float qf4[QKC * 16], kf4[QKC * 16];
    __shared__ float qf2[QKC * 4],  kf2[QKC * 4];
    const int b = blockIdx.x, t = threadIdx.x;
    const float* xb = x + b * Cc * LLEN;

    // adaptive avg pool to 4x4 (exact uniform pooling)
    for (int idx = t; idx < Cc * 16; idx += 256) {
        int c = idx >> 4, cell = idx & 15, i = cell >> 2, j = cell & 3;
        float s = 0.f;
        for (int y = 0; y < 8; y++)
#pragma unroll
            for (int xx = 0; xx < 8; xx++)
                s += xb[c * LLEN + (i * 8 + y) * 32 + j * 8 + xx];
        sp4[idx] = s * (1.f / 64.f);
    }
    __syncthreads();

    // rce 1x1 convs; pooled2 derived on the fly (avg of 2x2 pooled4 cells = exact 16x16 pool)
    if (t < C4) {
        float a4[16] = {}, a2[4] = {};
        for (int c = 0; c < Cc; c++) {
            const float w4 = rce_w[(2 * C4 + t) * Cc + c];
            const float w2 = rce_w[(1 * C4 + t) * Cc + c];
            const float* p = &sp4[c * 16];
#pragma unroll
            for (int cell = 0; cell < 16; cell++) a4[cell] += w4 * p[cell];
#pragma unroll
            for (int i = 0; i < 2; i++)
#pragma unroll
                for (int j = 0; j < 2; j++)
                    a2[i * 2 + j] += w2 * 0.25f *
                        (p[(2 * i) * 4 + 2 * j] + p[(2 * i) * 4 + 2 * j + 1] +
                         p[(2 * i + 1) * 4 + 2 * j] + p[(2 * i + 1) * 4 + 2 * j + 1]);
        }
        const float b4 = rce_b[2 * C4 + t], b2v = rce_b[1 * C4 + t];
#pragma unroll
        for (int cell = 0; cell < 16; cell++) f4[t * 16 + cell] = a4[cell] + b4;
#pragma unroll
        for (int cc = 0; cc < 4; cc++) f2[t * 4 + cc] = a2[cc] + b2v;
    }
    __syncthreads();

    // q/k 1x1 convs on tiny feats (bias folded in: upsample preserves constants)
    {
        const int qc = t >> 4, cell = t & 15;
        float aq = 0.f, ak = 0.f;
        for (int o = 0; o < C4; o++) {
            const float fv = f4[o * 16 + cell];
            aq += qw[qc * C4 + o] * fv;
            ak += kw[qc * C4 + o] * fv;
        }
        qf4[t] = aq + qb[qc]; kf4[t] = ak + kb[qc];
    }
    if (t < 64) {
        const int qc = t >> 2, cc = t & 3;
        float aq = 0.f, ak = 0.f;
        for (int o = 0; o < C4; o++) {
            const float fv = f2[o * 4 + cc];
            aq += qw[qc * C4 + o] * fv;
            ak += kw[qc * C4 + o] * fv;
        }
        qf2[t] = aq + qb[qc]; kf2[t] = ak + kb[qc];
    }
    __syncthreads();

    // bilinear upsample (align_corners=True) to full 32x32 for q,k
    const float st4 = 3.0f / 31.0f, st2 = 1.0f / 31.0f;
    for (int idx = t; idx < QKC * LLEN; idx += 256) {
        const int qc = idx >> 10, p = idx & 1023, r = p >> 5, cc = p & 31;
        // sz=4
        float pr = r * st4;  int lr = (int)pr; lr = lr > 2 ? 2 : lr; float fr = pr - lr;
        float pc = cc * st4; int lc = (int)pc; lc = lc > 2 ? 2 : lc; float fc = pc - lc;
        const float w00 = (1.f - fr) * (1.f - fc), w01 = (1.f - fr) * fc;
        const float w10 = fr * (1.f - fc),         w11 = fr * fc;
        const float* q4 = &qf4[qc * 16]; const float* k4 = &kf4[qc * 16];
        g_qk[qk_idx(0, 1, b, qc, p)] =
            w00 * q4[lr * 4 + lc] + w01 * q4[lr * 4 + lc + 1] +
            w10 * q4[(lr + 1) * 4 + lc] + w11 * q4[(lr + 1) * 4 + lc + 1];
        g_qk[qk_idx(1, 1, b, qc, p)] =
            w00 * k4[lr * 4 + lc] + w01 * k4[lr * 4 + lc + 1] +
            w10 * k4[(lr + 1) * 4 + lc] + w11 * k4[(lr + 1) * 4 + lc + 1];
        // sz=2 (lo always 0)
        const float fr2 = r * st2, fc2 = cc * st2;
        const float u00 = (1.f - fr2) * (1.f - fc2), u01 = (1.f - fr2) * fc2;
        const float u10 = fr2 * (1.f - fc2),          u11 = fr2 * fc2;
        const float* q2 = &qf2[qc * 4]; const float* k2 = &kf2[qc * 4];
        g_qk[qk_idx(0, 0, b, qc, p)] = u00 * q2[0] + u01 * q2[1] + u10 * q2[2] + u11 * q2[3];
        g_qk[qk_idx(1, 0, b, qc, p)] = u00 * k2[0] + u01 * k2[1] + u10 * k2[2] + u11 * k2[3];
    }
}

// ---------------- K3: sz=1 pyramid output = row-mean of value, broadcast ------------------
__global__ void k_mean() {
    const int c = blockIdx.x, b = blockIdx.y, t = threadIdx.x;
    const float* v = &g_value[(b * C4 + c) * LLEN];
    float s = 0.f;
    for (int i = t; i < LLEN; i += 256) s += v[i];
    __shared__ float red[256];
    red[t] = s; __syncthreads();
    for (int o = 128; o > 0; o >>= 1) { if (t < o) red[t] += red[t + o]; __syncthreads(); }
    const float mean = red[0] * (1.f / LLEN);
    float* out = &g_cat[(b * 3 * C4 + c) * LLEN];
    for (int i = t; i < LLEN; i += 256) out[i] = mean;
}

// ---------------- K4: energy + softmax -> attn probabilities (sz=2 and sz=4) --------------
__global__ void __launch_bounds__(256, 1) k_attn() {
    extern __shared__ float ks[];   // [1024][20] padded k, 80KB
    const int b = blockIdx.z, pyr = blockIdx.y;
    const int mbase = blockIdx.x * 128;
    const int t = threadIdx.x, w = t >> 5, lane = t & 31;
    const float* gq = &g_qk[qk_idx(0, pyr, b, 0, 0)];
    const float* gk = &g_qk[qk_idx(1, pyr, b, 0, 0)];
    for (int idx = t; idx < QKC * LLEN; idx += 256) {
        const int qc = idx >> 10, l = idx & 1023;
        ks[l * 20 + qc] = gk[qc * LLEN + l];
    }
    __syncthreads();
    float* pb = &g_attn[(size_t)(pyr * Nn + b) * LLEN * LLEN];

    for (int pr = 0; pr < 8; pr++) {
        const int ma = mbase + w * 16 + pr * 2;
        const int mb = ma + 1;
        float qa[16], qb[16];
#pragma unroll
        for (int j = 0; j < 16; j++) { qa[j] = gq[j * LLEN + ma]; qb[j] = gq[j * LLEN + mb]; }
        float ea[32], eb[32];
        float mxa = -1e30f, mxb = -1e30f;
#pragma unroll
        for (int i = 0; i < 32; i++) {
            const int l = i * 32 + lane;
            const float4* kp = (const float4*)&ks[l * 20];
            const float4 k0 = kp[0], k1 = kp[1], k2 = kp[2], k3 = kp[3];
            float sa = qa[0]*k0.x + qa[1]*k0.y + qa[2]*k0.z + qa[3]*k0.w
                     + qa[4]*k1.x + qa[5]*k1.y + qa[6]*k1.z + qa[7]*k1.w
                     + qa[8]*k2.x + qa[9]*k2.y + qa[10]*k2.z + qa[11]*k2.w
                     + qa[12]*k3.x + qa[13]*k3.y + qa[14]*k3.z + qa[15]*k3.w;
            float sb = qb[0]*k0.x + qb[1]*k0.y + qb[2]*k0.z + qb[3]*k0.w
                     + qb[4]*k1.x + qb[5]*k1.y + qb[6]*k1.z + qb[7]*k1.w
                     + qb[8]*k2.x + qb[9]*k2.y + qb[10]*k2.z + qb[11]*k2.w
                     + qb[12]*k3.x + qb[13]*k3.y + qb[14]*k3.z + qb[15]*k3.w;
            ea[i] = sa; eb[i] = sb;
            mxa = fmaxf(mxa, sa); mxb = fmaxf(mxb, sb);
        }
#pragma unroll
        for (int o = 16; o > 0; o >>= 1) {
            mxa = fmaxf(mxa, __shfl_xor_sync(0xffffffffu, mxa, o));
            mxb = fmaxf(mxb, __shfl_xor_sync(0xffffffffu, mxb, o));
        }
        float sma = 0.f, smb = 0.f;
#pragma unroll
        for (int i = 0; i < 32; i++) {
            ea[i] = __expf(ea[i] - mxa); sma += ea[i];
            eb[i] = __expf(eb[i] - mxb); smb += eb[i];
        }
#pragma unroll
        for (int o = 16; o > 0; o >>= 1) {
            sma += __shfl_xor_sync(0xffffffffu, sma, o);
            smb += __shfl_xor_sync(0xffffffffu, smb, o);
        }
        const float ia = 1.f / sma, ib = 1.f / smb;
        float* pa  = &pb[(size_t)ma * LLEN];
        float* pbr = &pb[(size_t)mb * LLEN];
#pragma unroll
        for (int i = 0; i < 32; i++) {
            pa[i * 32 + lane]  = ea[i] * ia;
            pbr[i * 32 + lane] = eb[i] * ib;
        }
    }
}

// ---------------- K5: out[c][m] = sum_l V[c][l] * P[m][l]  (A·B^T GEMM) -------------------
__global__ void k_outgemm() {
    __shared__ float As[32 * 68];
    __shared__ float Bs[32 * 68];
    const int z = blockIdx.z; const int b = z >> 1; const int pyr = z & 1;
    const int c0 = blockIdx.y * 64;
    const int m0 = blockIdx.x * 64;
    const float* V = g_value + b * C4 * LLEN;
    const float* P = g_attn + (size_t)(pyr * Nn + b) * LLEN * LLEN;
    const int t = threadIdx.x, ty = t >> 4, tx = t & 15;
    const int r = t >> 2, kq = (t & 3) * 8;
    float acc[4][4] = {};

    for (int kc = 0; kc < LLEN / 32; kc++) {
        const int l0 = kc * 32;
        __syncthreads();
        float4 a0 = *(const float4*)&V[(c0 + r) * LLEN + l0 + kq];
        float4 a1 = *(const float4*)&V[(c0 + r) * LLEN + l0 + kq + 4];
        As[(kq + 0) * 68 + r] = a0.x; As[(kq + 1) * 68 + r] = a0.y;
        As[(kq + 2) * 68 + r] = a0.z; As[(kq + 3) * 68 + r] = a0.w;
        As[(kq + 4) * 68 + r] = a1.x; As[(kq + 5) * 68 + r] = a1.y;
        As[(kq + 6) * 68 + r] = a1.z; As[(kq + 7) * 68 + r] = a1.w;
        float4 b0 = *(const float4*)&P[(size_t)(m0 + r) * LLEN + l0 + kq];
        float4 b1 = *(const float4*)&P[(size_t)(m0 + r) * LLEN + l0 + kq + 4];
        Bs[(kq + 0) * 68 + r] = b0.x; Bs[(kq + 1) * 68 + r] = b0.y;
        Bs[(kq + 2) * 68 + r] = b0.z; Bs[(kq + 3) * 68 + r] = b0.w;
        Bs[(kq + 4) * 68 + r] = b1.x; Bs[(kq + 5) * 68 + r] = b1.y;
        Bs[(kq + 6) * 68 + r] = b1.z; Bs[(kq + 7) * 68 + r] = b1.w;
        __syncthreads();
#pragma unroll
        for (int k = 0; k < 32; k++) {
            float4 av = *(const float4*)&As[k * 68 + ty * 4];
            float4 bv = *(const float4*)&Bs[k * 68 + tx * 4];
            acc[0][0] += av.x * bv.x; acc[0][1] += av.x * bv.y; acc[0][2] += av.x * bv.z; acc[0][3] += av.x * bv.w;
            acc[1][0] += av.y * bv.x; acc[1][1] += av.y * bv.y; acc[1][2] += av.y * bv.z; acc[1][3] += av.y * bv.w;
            acc[2][0] += av.z * bv.x; acc[2][1] += av.z * bv.y; acc[2][2] += av.z * bv.z; acc[2][3] += av.z * bv.w;
            acc[3][0] += av.w * bv.x; acc[3][1] += av.w * bv.y; acc[3][2] += av.w * bv.z; acc[3][3] += av.w * bv.w;
        }
    }
#pragma unroll
    for (int i = 0; i < 4; i++) {
        const int ch = C4 + pyr * C4 + c0 + ty * 4 + i;   // channels [128:256) sz2, [256:384) sz4
        float4 o;
        o.x = acc[i][0]; o.y = acc[i][1]; o.z = acc[i][2]; o.w = acc[i][3];
        *(float4*)&g_cat[(b * 3 * C4 + ch) * LLEN + m0 + tx * 4] = o;
    }
}

// ---------------- K6: fusion 3x3 conv (implicit GEMM, smem-tiled) -------------------------
__global__ void k_conv(const float* __restrict__ fw) {
    __shared__ float s_in[16 * 10 * 34];   // [ci][yy 0..9][xx 0..33] padded input, 21.25KB
    __shared__ float s_w[32 * 145];        // [co][ci*9+k] padded row 145, 18.1KB
    const int b = blockIdx.z, co0 = blockIdx.y * 32, y0 = blockIdx.x * 8;
    const int t = threadIdx.x;
    const int cog = t & 7, spg = t >> 3;
    const int y_l = spg >> 2, xb = (spg & 3) * 8;
    const float* catb = &g_cat[b * 3 * C4 * LLEN];
    float acc[4][8] = {};

    for (int cic = 0; cic < 24; cic++) {
        const int ci0 = cic * 16;
        __syncthreads();
        for (int idx = t; idx < 16 * 10 * 34; idx += 256) {
            const int ci = idx / 340, rem = idx % 340, yy = rem / 34, xx = rem % 34;
            const int gy = y0 + yy - 1, gx = xx - 1;
            float v = 0.f;
            if (gy >= 0 && gy < 32 && gx >= 0 && gx < 32)
                v = catb[(ci0 + ci) * LLEN + gy * 32 + gx];
            s_in[idx] = v;
        }
        for (int idx = t; idx < 32 * 144; idx += 256) {
            const int co = idx / 144, r2 = idx % 144;
            s_w[co * 145 + r2] = fw[(co0 + co) * 3456 + ci0 * 9 + r2];
        }
        __syncthreads();
        for (int ci = 0; ci < 16; ci++) {
#pragma unroll
            for (int ky = 0; ky < 3; ky++) {
                float rseg[10];
                const float* rp = &s_in[ci * 340 + (y_l + ky) * 34 + xb];
#pragma unroll
                for (int u = 0; u < 10; u++) rseg[u] = rp[u];
#pragma unroll
                for (int kx = 0; kx < 3; kx++) {
#pragma unroll
                    for (int i = 0; i < 4; i++) {
                        const float wv = s_w[(cog * 4 + i) * 145 + ci * 9 + ky * 3 + kx];
#pragma unroll
                        for (int u = 0; u < 8; u++) acc[i][u] += wv * rseg[u + kx];
                    }
                }
            }
        }
    }
#pragma unroll
    for (int i = 0; i < 4; i++) {
        float* yrow = &g_y[((size_t)b * Cc + co0 + cog * 4 + i) * LLEN + (y0 + y_l) * 32 + xb];
#pragma unroll
        for (int u = 0; u < 8; u++) yrow[u] = acc[i][u];
    }
}

// ---------------- K7: BN batch statistics per channel -------------------------------------
__global__ void k_stats(const float* __restrict__ bn_scale) {
    const int c = blockIdx.x, t = threadIdx.x;
    double s = 0.0, ss = 0.0;
    for (int idx = t; idx < Nn * LLEN; idx += 256) {
        const int bb = idx >> 10, l = idx & 1023;
        const float v = g_y[((size_t)bb * Cc + c) * LLEN + l];
        s += v; ss += (double)v * v;
    }
    __shared__ double rs[256], rq[256];
    rs[t] = s; rq[t] = ss; __syncthreads();
    for (int o = 128; o > 0; o >>= 1) {
        if (t < o) { rs[t] += rs[t + o]; rq[t] += rq[t + o]; }
        __syncthreads();
    }
    if (t == 0) {
        const double mean = rs[0] / (double)(Nn * LLEN);
        const double var  = rq[0] / (double)(Nn * LLEN) - mean * mean;
        g_stats[c * 2]     = (float)mean;
        g_stats[c * 2 + 1] = bn_scale[c] * rsqrtf((float)var + EPSf);
    }
}

// ---------------- K8: BN apply + ReLU + gamma*y + x ----------------------------------------
__global__ void k_final(const float* __restrict__ x, const float* __restrict__ bn_bias,
                        const float* __restrict__ gamma, float* __restrict__ out) {
    const int idx = blockIdx.x * 256 + threadIdx.x;  // 8,388,608 total
    const float g = gamma[0];
    const int c = (idx >> 10) & (Cc - 1);
    const float v = g_y[idx];
    float tt = (v - g_stats[c * 2]) * g_stats[c * 2 + 1] + bn_bias[c];
    tt = fmaxf(tt, 0.f);
    out[idx] = g * tt + x[idx];
}

// ---------------- launch ------------------------------------------------------------------
extern "C" void kernel_launch(void* const* d_in, const int* in_sizes, int n_in,
                              void* d_out, int out_size) {
    (void)in_sizes; (void)n_in; (void)out_size;
    const float* x        = (const float*)d_in[0];
    const float* rce_w    = (const float*)d_in[1];
    const float* rce_b    = (const float*)d_in[2];
    const float* q_w      = (const float*)d_in[3];
    const float* q_b      = (const float*)d_in[4];
    const float* k_w      = (const float*)d_in[5];
    const float* k_b      = (const float*)d_in[6];
    const float* value_w  = (const float*)d_in[7];
    const float* value_b  = (const float*)d_in[8];
    const float* fusion_w = (const float*)d_in[9];
    const float* bn_scale = (const float*)d_in[10];
    const float* bn_bias  = (const float*)d_in[11];
    const float* gamma    = (const float*)d_in[12];
    float* out = (float*)d_out;

    cudaFuncSetAttribute(k_attn, cudaFuncAttributeMaxDynamicSharedMemorySize, 81920);

    k_value_proj<<<dim3(16, 2, 16), 256>>>(x, value_w, value_b);
    k_prep<<<16, 256>>>(x, rce_w, rce_b, q_w, q_b, k_w, k_b);
    k_mean<<<dim3(128, 16), 256>>>();
    k_attn<<<dim3(8, 2, 16), 256, 81920>>>();
    k_outgemm<<<dim3(16, 2, 32), 256>>>();
    k_conv<<<dim3(4, 16, 16), 256>>>(fusion_w);
    k_stats<<<512, 256>>>(bn_scale);
    k_final<<<32768, 256>>>(x, bn_bias, gamma, out);
}

// round 2
// speedup vs baseline: 1.1116x; 1.1116x over previous
#include <cuda_runtime.h>
#include <math.h>

#define Nn 16
#define Cc 512
#define C4 128
#define QKC 16
#define LLEN 1024
#define EPSf 1e-5f

// ---------------- scratch (device globals; no allocation allowed) ----------------
__device__ float g_value[Nn * C4 * LLEN];                 // 8 MB   proj_value
__device__ float g_qk[2 * 2 * Nn * QKC * LLEN];           // 4 MB   [q/k][pyr][b][qc][l]
__device__ float g_attn[2 * Nn * LLEN * LLEN];            // 134 MB [pyr][b][m][l] probabilities
__device__ float g_cat[Nn * 2 * C4 * LLEN];               // 16 MB  sz2/sz4 pyramid outputs
__device__ float g_y[Nn * Cc * LLEN];                     // 33 MB  conv output pre-BN
__device__ float g_stats[Cc * 2];                         // per-channel mean, scale*rstd
__device__ float g_mean[Nn * C4];                         // sz=1 pyramid (row means of value)
__device__ float g_wsum[9 * Cc * C4];                     // border-pattern weight sums (sz1 chans)
__device__ float g_contrib[Nn * 9 * Cc];                  // constant-channel conv contribution
__device__ float g_wt[2304 * Cc];                         // transposed fusion weights [ci*9+k][co]

__device__ __forceinline__ int qk_idx(int g, int py, int b, int qc, int l) {
    return (((g * 2 + py) * Nn + b) * QKC + qc) * LLEN + l;
}

// ---------------- K1: value projection GEMM: out = value_w(128x512) @ x(b,512,1024) + b ----
__global__ void k_value_proj(const float* __restrict__ x,
                             const float* __restrict__ w,
                             const float* __restrict__ bias) {
    __shared__ float As[32 * 68];
    __shared__ float Bs[32 * 68];
    const int b  = blockIdx.z;
    const int m0 = blockIdx.y * 64;
    const int n0 = blockIdx.x * 64;
    const float* xb = x + b * Cc * LLEN;
    const int t  = threadIdx.x;
    const int ty = t >> 4, tx = t & 15;
    const int am = t >> 2, akq = (t & 3) * 8;
    const int bk = t >> 3, bnq = (t & 7) * 8;
    float acc[4][4] = {};

    for (int kc = 0; kc < Cc / 32; kc++) {
        const int k0 = kc * 32;
        __syncthreads();
        float4 a0 = *(const float4*)&w[(m0 + am) * Cc + k0 + akq];
        float4 a1 = *(const float4*)&w[(m0 + am) * Cc + k0 + akq + 4];
        As[(akq + 0) * 68 + am] = a0.x; As[(akq + 1) * 68 + am] = a0.y;
        As[(akq + 2) * 68 + am] = a0.z; As[(akq + 3) * 68 + am] = a0.w;
        As[(akq + 4) * 68 + am] = a1.x; As[(akq + 5) * 68 + am] = a1.y;
        As[(akq + 6) * 68 + am] = a1.z; As[(akq + 7) * 68 + am] = a1.w;
        float4 b0 = *(const float4*)&xb[(k0 + bk) * LLEN + n0 + bnq];
        float4 b1 = *(const float4*)&xb[(k0 + bk) * LLEN + n0 + bnq + 4];
        *(float4*)&Bs[bk * 68 + bnq]     = b0;
        *(float4*)&Bs[bk * 68 + bnq + 4] = b1;
        __syncthreads();
#pragma unroll
        for (int k = 0; k < 32; k++) {
            float4 av = *(const float4*)&As[k * 68 + ty * 4];
            float4 bv = *(const float4*)&Bs[k * 68 + tx * 4];
            acc[0][0] += av.x * bv.x; acc[0][1] += av.x * bv.y; acc[0][2] += av.x * bv.z; acc[0][3] += av.x * bv.w;
            acc[1][0] += av.y * bv.x; acc[1][1] += av.y * bv.y; acc[1][2] += av.y * bv.z; acc[1][3] += av.y * bv.w;
            acc[2][0] += av.z * bv.x; acc[2][1] += av.z * bv.y; acc[2][2] += av.z * bv.z; acc[2][3] += av.z * bv.w;
            acc[3][0] += av.w * bv.x; acc[3][1] += av.w * bv.y; acc[3][2] += av.w * bv.z; acc[3][3] += av.w * bv.w;
        }
    }
#pragma unroll
    for (int i = 0; i < 4; i++) {
        const int c = m0 + ty * 4 + i;
        const float bs = bias[c];
        float4 o;
        o.x = acc[i][0] + bs; o.y = acc[i][1] + bs; o.z = acc[i][2] + bs; o.w = acc[i][3] + bs;
        *(float4*)&g_value[(b * C4 + c) * LLEN + n0 + tx * 4] = o;
    }
}

// ---------------- K2: per-batch pooling + rce + q/k feats + bilinear upsample -------------
__global__ void k_prep(const float* __restrict__ x,
                       const float* __restrict__ rce_w, const float* __restrict__ rce_b,
                       const float* __restrict__ qw, const float* __restrict__ qb,
                       const float* __restrict__ kw, const float* __restrict__ kb) {
    __shared__ float sp4[Cc * 16];
    __shared__ float f4[C4 * 16];
    __shared__ float f2[C4 * 4];
    __shared__ float qf4[QKC * 16], kf4[QKC * 16];
    __shared__ float qf2[QKC * 4],  kf2[QKC * 4];
    const int b = blockIdx.x, t = threadIdx.x;
    const float* xb = x + b * Cc * LLEN;

    for (int idx = t; idx < Cc * 16; idx += 256) {
        int c = idx >> 4, cell = idx & 15, i = cell >> 2, j = cell & 3;
        float s = 0.f;
        for (int y = 0; y < 8; y++)
#pragma unroll
            for (int xx = 0; xx < 8; xx++)
                s += xb[c * LLEN + (i * 8 + y) * 32 + j * 8 + xx];
        sp4[idx] = s * (1.f / 64.f);
    }
    __syncthreads();

    if (t < C4) {
        float a4[16] = {}, a2[4] = {};
        for (int c = 0; c < Cc; c++) {
            const float w4 = rce_w[(2 * C4 + t) * Cc + c];
            const float w2 = rce_w[(1 * C4 + t) * Cc + c];
            const float* p = &sp4[c * 16];
#pragma unroll
            for (int cell = 0; cell < 16; cell++) a4[cell] += w4 * p[cell];
#pragma unroll
            for (int i = 0; i < 2; i++)
#pragma unroll
                for (int j = 0; j < 2; j++)
                    a2[i * 2 + j] += w2 * 0.25f *
                        (p[(2 * i) * 4 + 2 * j] + p[(2 * i) * 4 + 2 * j + 1] +
                         p[(2 * i + 1) * 4 + 2 * j] + p[(2 * i + 1) * 4 + 2 * j + 1]);
        }
        const float b4 = rce_b[2 * C4 + t], b2v = rce_b[1 * C4 + t];
#pragma unroll
        for (int cell = 0; cell < 16; cell++) f4[t * 16 + cell] = a4[cell] + b4;
#pragma unroll
        for (int cc = 0; cc < 4; cc++) f2[t * 4 + cc] = a2[cc] + b2v;
    }
    __syncthreads();

    {
        const int qc = t >> 4, cell = t & 15;
        float aq = 0.f, ak = 0.f;
        for (int o = 0; o < C4; o++) {
            const float fv = f4[o * 16 + cell];
            aq += qw[qc * C4 + o] * fv;
            ak += kw[qc * C4 + o] * fv;
        }
        qf4[t] = aq + qb[qc]; kf4[t] = ak + kb[qc];
    }
    if (t < 64) {
        const int qc = t >> 2, cc = t & 3;
        float aq = 0.f, ak = 0.f;
        for (int o = 0; o < C4; o++) {
            const float fv = f2[o * 4 + cc];
            aq += qw[qc * C4 + o] * fv;
            ak += kw[qc * C4 + o] * fv;
        }
        qf2[t] = aq + qb[qc]; kf2[t] = ak + kb[qc];
    }
    __syncthreads();

    const float st4 = 3.0f / 31.0f, st2 = 1.0f / 31.0f;
    for (int idx = t; idx < QKC * LLEN; idx += 256) {
        const int qc = idx >> 10, p = idx & 1023, r = p >> 5, cc = p & 31;
        float pr = r * st4;  int lr = (int)pr; lr = lr > 2 ? 2 : lr; float fr = pr - lr;
        float pc = cc * st4; int lc = (int)pc; lc = lc > 2 ? 2 : lc; float fc = pc - lc;
        const float w00 = (1.f - fr) * (1.f - fc), w01 = (1.f - fr) * fc;
        const float w10 = fr * (1.f - fc),         w11 = fr * fc;
        const float* q4 = &qf4[qc * 16]; const float* k4 = &kf4[qc * 16];
        g_qk[qk_idx(0, 1, b, qc, p)] =
            w00 * q4[lr * 4 + lc] + w01 * q4[lr * 4 + lc + 1] +
            w10 * q4[(lr + 1) * 4 + lc] + w11 * q4[(lr + 1) * 4 + lc + 1];
        g_qk[qk_idx(1, 1, b, qc, p)] =
            w00 * k4[lr * 4 + lc] + w01 * k4[lr * 4 + lc + 1] +
            w10 * k4[(lr + 1) * 4 + lc] + w11 * k4[(lr + 1) * 4 + lc + 1];
        const float fr2 = r * st2, fc2 = cc * st2;
        const float u00 = (1.f - fr2) * (1.f - fc2), u01 = (1.f - fr2) * fc2;
        const float u10 = fr2 * (1.f - fc2),          u11 = fr2 * fc2;
        const float* q2 = &qf2[qc * 4]; const float* k2 = &kf2[qc * 4];
        g_qk[qk_idx(0, 0, b, qc, p)] = u00 * q2[0] + u01 * q2[1] + u10 * q2[2] + u11 * q2[3];
        g_qk[qk_idx(1, 0, b, qc, p)] = u00 * k2[0] + u01 * k2[1] + u10 * k2[2] + u11 * k2[3];
    }
}

// ---------------- K3: sz=1 pyramid -> just the mean per (b, c) ----------------------------
__global__ void k_mean() {
    const int c = blockIdx.x, b = blockIdx.y, t = threadIdx.x;
    const float* v = &g_value[(b * C4 + c) * LLEN];
    float s = 0.f;
    for (int i = t; i < LLEN; i += 256) s += v[i];
    __shared__ float red[256];
    red[t] = s; __syncthreads();
    for (int o = 128; o > 0; o >>= 1) { if (t < o) red[t] += red[t + o]; __syncthreads(); }
    if (t == 0) g_mean[b * C4 + c] = red[0] * (1.f / LLEN);
}

// ---------------- K3b: border-pattern weight sums for constant channels -------------------
// pat = rowtype*3 + coltype; rowtype 0=top,1=mid,2=bot; coltype 0=left,1=mid,2=right
__global__ void k_wsum(const float* __restrict__ fw) {
    const int co = blockIdx.x, ci = threadIdx.x;   // ci in [0,128): sz1 original channels
    float w[9];
#pragma unroll
    for (int k = 0; k < 9; k++) w[k] = fw[co * 3456 + ci * 9 + k];
#pragma unroll
    for (int rt = 0; rt < 3; rt++) {
        const int kylo = (rt == 0) ? 1 : 0, kyhi = (rt == 2) ? 1 : 2;
#pragma unroll
        for (int ct = 0; ct < 3; ct++) {
            const int kxlo = (ct == 0) ? 1 : 0, kxhi = (ct == 2) ? 1 : 2;
            float s = 0.f;
            for (int ky = kylo; ky <= kyhi; ky++)
                for (int kx = kxlo; kx <= kxhi; kx++)
                    s += w[ky * 3 + kx];
            g_wsum[((rt * 3 + ct) * Cc + co) * C4 + ci] = s;
        }
    }
}

// ---------------- K3c: constant-channel conv contribution per (b, pat, co) ----------------
__global__ void k_const() {
    __shared__ float sm[C4];
    const int b = blockIdx.x, co = threadIdx.x;   // 512 threads
    if (co < C4) sm[co] = g_mean[b * C4 + co];
    __syncthreads();
#pragma unroll
    for (int pat = 0; pat < 9; pat++) {
        const float* ws = &g_wsum[(pat * Cc + co) * C4];
        float s = 0.f;
        for (int ci = 0; ci < C4; ci++) s += sm[ci] * ws[ci];
        g_contrib[(b * 9 + pat) * Cc + co] = s;
    }
}

// ---------------- K3d: transpose fusion weights (sz2/sz4 part) -> [ci*9+k][co] ------------
__global__ void k_wt(const float* __restrict__ fw) {
    const int idx = blockIdx.x * 256 + threadIdx.x;   // 2304*512
    const int co = idx / 2304, r = idx % 2304;
    g_wt[r * Cc + co] = fw[co * 3456 + 1152 + r];
}

// ---------------- K4: energy + softmax -> attn probabilities (sz=2 and sz=4) --------------
__global__ void __launch_bounds__(256) k_attn() {
    extern __shared__ float ks[];   // [1024][20] padded k, 80KB
    const int b = blockIdx.z, pyr = blockIdx.y;
    const int mbase = blockIdx.x * 128;
    const int t = threadIdx.x, w = t >> 5, lane = t & 31;
    const float* gq = &g_qk[qk_idx(0, pyr, b, 0, 0)];
    const float* gk = &g_qk[qk_idx(1, pyr, b, 0, 0)];
    for (int idx = t; idx < QKC * LLEN; idx += 256) {
        const int qc = idx >> 10, l = idx & 1023;
        ks[l * 20 + qc] = gk[qc * LLEN + l];
    }
    __syncthreads();
    float* pb = &g_attn[(size_t)(pyr * Nn + b) * LLEN * LLEN];

    for (int pr = 0; pr < 16; pr++) {
        const int m = mbase + pr * 8 + w;
        float q[16];
#pragma unroll
        for (int j = 0; j < 16; j++) q[j] = gq[j * LLEN + m];
        float e[32];
        float mx = -1e30f;
#pragma unroll
        for (int i = 0; i < 32; i++) {
            const int l = i * 32 + lane;
            const float4* kp = (const float4*)&ks[l * 20];
            const float4 k0 = kp[0], k1 = kp[1], k2 = kp[2], k3 = kp[3];
            float s = q[0]*k0.x + q[1]*k0.y + q[2]*k0.z + q[3]*k0.w
                    + q[4]*k1.x + q[5]*k1.y + q[6]*k1.z + q[7]*k1.w
                    + q[8]*k2.x + q[9]*k2.y + q[10]*k2.z + q[11]*k2.w
                    + q[12]*k3.x + q[13]*k3.y + q[14]*k3.z + q[15]*k3.w;
            e[i] = s;
            mx = fmaxf(mx, s);
        }
#pragma unroll
        for (int o = 16; o > 0; o >>= 1)
            mx = fmaxf(mx, __shfl_xor_sync(0xffffffffu, mx, o));
        float sm = 0.f;
#pragma unroll
        for (int i = 0; i < 32; i++) { e[i] = __expf(e[i] - mx); sm += e[i]; }
#pragma unroll
        for (int o = 16; o > 0; o >>= 1)
            sm += __shfl_xor_sync(0xffffffffu, sm, o);
        const float inv = 1.f / sm;
        float* pa = &pb[(size_t)m * LLEN];
#pragma unroll
        for (int i = 0; i < 32; i++)
            pa[i * 32 + lane] = e[i] * inv;
    }
}

// ---------------- K5: out[c][m] = sum_l V[c][l] * P[m][l]  (A·B^T GEMM) -------------------
__global__ void k_outgemm() {
    __shared__ float As[32 * 68];
    __shared__ float Bs[32 * 68];
    const int z = blockIdx.z; const int b = z >> 1; const int pyr = z & 1;
    const int c0 = blockIdx.y * 64;
    const int m0 = blockIdx.x * 64;
    const float* V = g_value + b * C4 * LLEN;
    const float* P = g_attn + (size_t)(pyr * Nn + b) * LLEN * LLEN;
    const int t = threadIdx.x, ty = t >> 4, tx = t & 15;
    const int r = t >> 2, kq = (t & 3) * 8;
    float acc[4][4] = {};

    for (int kc = 0; kc < LLEN / 32; kc++) {
        const int l0 = kc * 32;
        __syncthreads();
        float4 a0 = *(const float4*)&V[(c0 + r) * LLEN + l0 + kq];
        float4 a1 = *(const float4*)&V[(c0 + r) * LLEN + l0 + kq + 4];
        As[(kq + 0) * 68 + r] = a0.x; As[(kq + 1) * 68 + r] = a0.y;
        As[(kq + 2) * 68 + r] = a0.z; As[(kq + 3) * 68 + r] = a0.w;
        As[(kq + 4) * 68 + r] = a1.x; As[(kq + 5) * 68 + r] = a1.y;
        As[(kq + 6) * 68 + r] = a1.z; As[(kq + 7) * 68 + r] = a1.w;
        float4 b0 = *(const float4*)&P[(size_t)(m0 + r) * LLEN + l0 + kq];
        float4 b1 = *(const float4*)&P[(size_t)(m0 + r) * LLEN + l0 + kq + 4];
        Bs[(kq + 0) * 68 + r] = b0.x; Bs[(kq + 1) * 68 + r] = b0.y;
        Bs[(kq + 2) * 68 + r] = b0.z; Bs[(kq + 3) * 68 + r] = b0.w;
        Bs[(kq + 4) * 68 + r] = b1.x; Bs[(kq + 5) * 68 + r] = b1.y;
        Bs[(kq + 6) * 68 + r] = b1.z; Bs[(kq + 7) * 68 + r] = b1.w;
        __syncthreads();
#pragma unroll
        for (int k = 0; k < 32; k++) {
            float4 av = *(const float4*)&As[k * 68 + ty * 4];
            float4 bv = *(const float4*)&Bs[k * 68 + tx * 4];
            acc[0][0] += av.x * bv.x; acc[0][1] += av.x * bv.y; acc[0][2] += av.x * bv.z; acc[0][3] += av.x * bv.w;
            acc[1][0] += av.y * bv.x; acc[1][1] += av.y * bv.y; acc[1][2] += av.y * bv.z; acc[1][3] += av.y * bv.w;
            acc[2][0] += av.z * bv.x; acc[2][1] += av.z * bv.y; acc[2][2] += av.z * bv.z; acc[2][3] += av.z * bv.w;
            acc[3][0] += av.w * bv.x; acc[3][1] += av.w * bv.y; acc[3][2] += av.w * bv.z; acc[3][3] += av.w * bv.w;
        }
    }
#pragma unroll
    for (int i = 0; i < 4; i++) {
        const int ch = pyr * C4 + c0 + ty * 4 + i;   // channels [0:128) sz2, [128:256) sz4
        float4 o;
        o.x = acc[i][0]; o.y = acc[i][1]; o.z = acc[i][2]; o.w = acc[i][3];
        *(float4*)&g_cat[(b * 2 * C4 + ch) * LLEN + m0 + tx * 4] = o;
    }
}

// ---------------- K6: fusion 3x3 conv over sz2/sz4 channels (implicit GEMM) ---------------
__global__ void __launch_bounds__(256, 2) k_conv() {
    __shared__ float s_in[16 * 360];   // [ci][yy 0..9][xx 0..35] padded input, 23040 B
    __shared__ float s_w[144 * 32];    // [ci*9+k][co] 18432 B
    const int b = blockIdx.z, co0 = blockIdx.y * 32, y0 = blockIdx.x * 8;
    const int t = threadIdx.x;
    const int cog = t & 7, spg = t >> 3;
    const int y_l = spg >> 2, xb = (spg & 3) * 8;
    const float* catb = &g_cat[b * 2 * C4 * LLEN];
    float acc[4][8] = {};

    for (int cic = 0; cic < 16; cic++) {
        const int ci0 = cic * 16;
        __syncthreads();
        for (int idx = t; idx < 16 * 360; idx += 256) {
            const int ci = idx / 360, rem = idx % 360, yy = rem / 36, xx = rem % 36;
            const int gy = y0 + yy - 1, gx = xx - 1;
            float v = 0.f;
            if (gy >= 0 && gy < 32 && gx >= 0 && gx < 32 && xx < 34)
                v = catb[(ci0 + ci) * LLEN + gy * 32 + gx];
            s_in[idx] = v;
        }
        // transposed weights: g_wt rows ci0*9 .. ci0*9+143, cols co0..co0+31
        for (int idx = t; idx < 144 * 32; idx += 256) {
            const int rr = idx >> 5, co = idx & 31;
            s_w[idx] = g_wt[(ci0 * 9 + rr) * Cc + co0 + co];
        }
        __syncthreads();
        for (int ci = 0; ci < 16; ci++) {
#pragma unroll
            for (int ky = 0; ky < 3; ky++) {
                const float* rp = &s_in[ci * 360 + (y_l + ky) * 36 + xb];
                const float4 rA = *(const float4*)rp;
                const float4 rB = *(const float4*)(rp + 4);
                const float r8 = rp[8], r9 = rp[9];
                const float rseg[10] = {rA.x, rA.y, rA.z, rA.w,
                                        rB.x, rB.y, rB.z, rB.w, r8, r9};
#pragma unroll
                for (int kx = 0; kx < 3; kx++) {
                    const float4 wv = *(const float4*)&s_w[(ci * 9 + ky * 3 + kx) * 32 + cog * 4];
#pragma unroll
                    for (int u = 0; u < 8; u++) {
                        acc[0][u] += wv.x * rseg[u + kx];
                        acc[1][u] += wv.y * rseg[u + kx];
                        acc[2][u] += wv.z * rseg[u + kx];
                        acc[3][u] += wv.w * rseg[u + kx];
                    }
                }
            }
        }
    }
    // epilogue: add constant-channel contribution by border pattern
    const int y = y0 + y_l;
    const int rt = (y == 0) ? 0 : ((y == 31) ? 2 : 1);
    const float* cb = &g_contrib[(size_t)b * 9 * Cc];
#pragma unroll
    for (int i = 0; i < 4; i++) {
        const int co = co0 + cog * 4 + i;
        const float cL = cb[(rt * 3 + 0) * Cc + co];
        const float cM = cb[(rt * 3 + 1) * Cc + co];
        const float cR = cb[(rt * 3 + 2) * Cc + co];
        float* yrow = &g_y[((size_t)b * Cc + co) * LLEN + y * 32 + xb];
#pragma unroll
        for (int u = 0; u < 8; u++) {
            const int xg = xb + u;
            const float cc = (xg == 0) ? cL : ((xg == 31) ? cR : cM);
            yrow[u] = acc[i][u] + cc;
        }
    }
}

// ---------------- K7: BN batch statistics per channel -------------------------------------
__global__ void k_stats(const float* __restrict__ bn_scale) {
    const int c = blockIdx.x, t = threadIdx.x;
    double s = 0.0, ss = 0.0;
    for (int idx = t; idx < Nn * LLEN; idx += 256) {
        const int bb = idx >> 10, l = idx & 1023;
        const float v = g_y[((size_t)bb * Cc + c) * LLEN + l];
        s += v; ss += (double)v * v;
    }
    __shared__ double rs[256], rq[256];
    rs[t] = s; rq[t] = ss; __syncthreads();
    for (int o = 128; o > 0; o >>= 1) {
        if (t < o) { rs[t] += rs[t + o]; rq[t] += rq[t + o]; }
        __syncthreads();
    }
    if (t == 0) {
        const double mean = rs[0] / (double)(Nn * LLEN);
        const double var  = rq[0] / (double)(Nn * LLEN) - mean * mean;
        g_stats[c * 2]     = (float)mean;
        g_stats[c * 2 + 1] = bn_scale[c] * rsqrtf((float)var + EPSf);
    }
}

// ---------------- K8: BN apply + ReLU + gamma*y + x ----------------------------------------
__global__ void k_final(const float* __restrict__ x, const float* __restrict__ bn_bias,
                        const float* __restrict__ gamma, float* __restrict__ out) {
    const int idx = blockIdx.x * 256 + threadIdx.x;
    const float g = gamma[0];
    const int c = (idx >> 10) & (Cc - 1);
    const float v = g_y[idx];
    float tt = (v - g_stats[c * 2]) * g_stats[c * 2 + 1] + bn_bias[c];
    tt = fmaxf(tt, 0.f);
    out[idx] = g * tt + x[idx];
}

// ---------------- launch ------------------------------------------------------------------
extern "C" void kernel_launch(void* const* d_in, const int* in_sizes, int n_in,
                              void* d_out, int out_size) {
    (void)in_sizes; (void)n_in; (void)out_size;
    const float* x        = (const float*)d_in[0];
    const float* rce_w    = (const float*)d_in[1];
    const float* rce_b    = (const float*)d_in[2];
    const float* q_w      = (const float*)d_in[3];
    const float* q_b      = (const float*)d_in[4];
    const float* k_w      = (const float*)d_in[5];
    const float* k_b      = (const float*)d_in[6];
    const float* value_w  = (const float*)d_in[7];
    const float* value_b  = (const float*)d_in[8];
    const float* fusion_w = (const float*)d_in[9];
    const float* bn_scale = (const float*)d_in[10];
    const float* bn_bias  = (const float*)d_in[11];
    const float* gamma    = (const float*)d_in[12];
    float* out = (float*)d_out;

    cudaFuncSetAttribute(k_attn, cudaFuncAttributeMaxDynamicSharedMemorySize, 81920);

    k_value_proj<<<dim3(16, 2, 16), 256>>>(x, value_w, value_b);
    k_prep<<<16, 256>>>(x, rce_w, rce_b, q_w, q_b, k_w, k_b);
    k_mean<<<dim3(128, 16), 256>>>();
    k_wsum<<<512, 128>>>(fusion_w);
    k_wt<<<4608, 256>>>(fusion_w);
    k_const<<<16, 512>>>();
    k_attn<<<dim3(8, 2, 16), 256, 81920>>>();
    k_outgemm<<<dim3(16, 2, 32), 256>>>();
    k_conv<<<dim3(4, 16, 16), 256>>>();
    k_stats<<<512, 256>>>(bn_scale);
    k_final<<<32768, 256>>>(x, bn_bias, gamma, out);
}